// round 7
// baseline (speedup 1.0000x reference)
#include <cuda_runtime.h>
#include <cuda_bf16.h>

// B=1, C=32, H=128, W=256. TWO warps per right-feature row: warp half=0
// owns j in [0,128), half=1 owns [128,256). Each lane holds 4 contiguous
// elements; register exclusive prefix + warp shuffle scan builds a
// WITHIN-HALF exclusive prefix in smem. Epilogue applies the half-0 row
// total conditionally: E(j) = raw[j] + (j>=128 ? totA : 0).
// 8192 warps total (vs 4096 in R5) -> restores latency hiding.

#define C_CH   32
#define H_DIM  128
#define W_DIM  256
#define FULLM  0xFFFFFFFFu
#define ROWS_PER_BLOCK 4
#define EPAD   260            // 257 entries padded

__global__ __launch_bounds__(256) void gcnet_halfrow_kernel(
        const float* __restrict__ feaR,
        const int* __restrict__ p_min,
        const int* __restrict__ p_max,
        float* __restrict__ out) {
    const int lane = threadIdx.x & 31;
    const int wrp  = threadIdx.x >> 5;          // 0..7
    const int rib  = wrp >> 1;                  // row in block 0..3
    const int half = wrp & 1;                   // 0: j<128, 1: j>=128
    const int row  = blockIdx.x * ROWS_PER_BLOCK + rib;   // 0..4095
    const int cr   = row >> 7;
    const int h    = row & 127;

    const int dmin = p_min[0] / 2;
    const int dmax = p_max[0] / 2;
    const int D    = dmax - dmin;
    const float mean_d  = 0.5f * (float)(dmin + dmax - 1);
    const float S_total = mean_d * (float)D;

    __shared__ float sEp[ROWS_PER_BLOCK][EPAD];
    __shared__ float sEq[ROWS_PER_BLOCK][EPAD];
    __shared__ float sTotP[ROWS_PER_BLOCK];     // half-0 row totals
    __shared__ float sTotQ[ROWS_PER_BLOCK];
    float* Ep = sEp[rib];
    float* Eq = sEq[rib];

    const int rowbase = row * W_DIM;
    const int j0 = half * 128 + 4 * lane;       // first element this lane owns

    // ---- load 4 contiguous elements, exp, register exclusive prefix ----
    const float4 a = *(const float4*)(feaR + rowbase + j0);
    float p0 = __expf(a.x), p1 = __expf(a.y), p2 = __expf(a.z), p3 = __expf(a.w);
    const float jf = (float)j0;

    // exclusive prefixes within the 4-element run
    float ep0 = 0.0f,        eq0 = 0.0f;
    float ep1 = p0,          eq1 = jf * p0;
    float ep2 = ep1 + p1,    eq2 = fmaf(jf + 1.0f, p1, eq1);
    float ep3 = ep2 + p2,    eq3 = fmaf(jf + 2.0f, p2, eq2);
    float tot_p = ep3 + p3,  tot_q = fmaf(jf + 3.0f, p3, eq3);

    // ---- warp inclusive scan of lane totals ----
    float ip = tot_p, iq = tot_q;
    #pragma unroll
    for (int off = 1; off < 32; off <<= 1) {
        float tp = __shfl_up_sync(FULLM, ip, off);
        float tq = __shfl_up_sync(FULLM, iq, off);
        if (lane >= off) { ip += tp; iq += tq; }
    }
    const float offp = ip - tot_p;              // within-half exclusive offset
    const float offq = iq - tot_q;

    // ---- write within-half exclusive prefix entries ----
    float4 v;
    v.x = ep0 + offp; v.y = ep1 + offp; v.z = ep2 + offp; v.w = ep3 + offp;
    *(float4*)(Ep + j0) = v;
    v.x = eq0 + offq; v.y = eq1 + offq; v.z = eq2 + offq; v.w = eq3 + offq;
    *(float4*)(Eq + j0) = v;
    if (lane == 31) {
        if (half == 0) { sTotP[rib] = ip; sTotQ[rib] = iq; }
        else           { Ep[W_DIM] = ip; Eq[W_DIM] = iq; }  // raw excl @256
    }

    // ---- left channel constant fill (independent of scan; before sync) ----
    {
        float4 cst = make_float4(mean_d, mean_d, mean_d, mean_d);
        *(float4*)(out + (cr * H_DIM + h) * W_DIM + j0) = cst;
    }

    __syncthreads();

    const float totA_p = sTotP[rib];
    const float totA_q = sTotQ[rib];

    // ---- 4 outputs per lane at w = half*128 + lane + 32*i ----
    float* outR = out + ((cr + C_CH) * H_DIM + h) * W_DIM;
    #pragma unroll
    for (int i = 0; i < 4; ++i) {
        const int w = half * 128 + lane + 32 * i;
        int dlo = dmin > (w - W_DIM + 1) ? dmin : (w - W_DIM + 1);
        int dhi = (dmax - 1) < w ? (dmax - 1) : w;
        int nv  = dhi - dlo + 1;
        float denv = 0.0f, numv = 0.0f, Sv = 0.0f;
        if (nv > 0) {
            const int jlo  = w - dhi;
            const int jhi1 = w - dlo + 1;
            const float eplo = Ep[jlo]  + ((jlo  >= 128) ? totA_p : 0.0f);
            const float ephi = Ep[jhi1] + ((jhi1 >= 128) ? totA_p : 0.0f);
            const float eqlo = Eq[jlo]  + ((jlo  >= 128) ? totA_q : 0.0f);
            const float eqhi = Eq[jhi1] + ((jhi1 >= 128) ? totA_q : 0.0f);
            denv = ephi - eplo;
            numv = (float)w * denv - (eqhi - eqlo);
            Sv   = 0.5f * (float)(dlo + dhi) * (float)nv;
        } else {
            nv = 0;
        }
        const float den = (float)(D - nv) + denv;
        const float num = (S_total - Sv) + numv;
        outR[w] = __fdividef(num, den);
    }
}

extern "C" void kernel_launch(void* const* d_in, const int* in_sizes, int n_in,
                              void* d_out, int out_size) {
    // metadata order: feaL (unused), feaR, min_disp, max_disp
    const float* feaR = (const float*)d_in[1];
    const int* p_min  = (const int*)d_in[2];
    const int* p_max  = (const int*)d_in[3];
    float* out = (float*)d_out;

    const int rows = C_CH * H_DIM;                       // 4096
    gcnet_halfrow_kernel<<<rows / ROWS_PER_BLOCK, 256>>>(feaR, p_min, p_max, out);
}

// round 8
// speedup vs baseline: 1.2444x; 1.2444x over previous
#include <cuda_runtime.h>

// B=1, C=32, H=128, W=256. Two warps per right-feature row (half 0: j<128,
// half 1: j>=128). Register exclusive prefix + warp shuffle scan; half-0
// total published via smem so ALL prefix entries are globally correct
// (no conditionals in the epilogue). E[j] = float2(P[j], Q[j]) merged so
// each window lookup is one LDS.64. Outputs with full disparity windows
// (w >= dmax-1, warp-uniform per group) take a short path:
//   out = w - (Q[w-dmin+1]-Q[w-dmax+1]) / (P[w-dmin+1]-P[w-dmax+1]).

#define C_CH   32
#define H_DIM  128
#define W_DIM  256
#define FULLM  0xFFFFFFFFu
#define ROWS_PER_BLOCK 4
#define E2PAD  260           // 257 float2 entries, padded

__global__ __launch_bounds__(256) void gcnet_v7_kernel(
        const float* __restrict__ feaR,
        const int* __restrict__ p_min,
        const int* __restrict__ p_max,
        float* __restrict__ out) {
    const int lane = threadIdx.x & 31;
    const int wrp  = threadIdx.x >> 5;          // 0..7
    const int rib  = wrp >> 1;                  // row in block 0..3
    const int half = wrp & 1;                   // 0: j<128, 1: j>=128
    const int row  = blockIdx.x * ROWS_PER_BLOCK + rib;   // 0..4095
    const int cr   = row >> 7;
    const int h    = row & 127;

    const int dmin = p_min[0] / 2;
    const int dmax = p_max[0] / 2;
    const int D    = dmax - dmin;
    const float mean_d  = 0.5f * (float)(dmin + dmax - 1);
    const float S_total = mean_d * (float)D;

    __shared__ float2 sE[ROWS_PER_BLOCK][E2PAD];
    __shared__ float2 sTot[ROWS_PER_BLOCK];     // half-0 (P,Q) totals
    float2* E = sE[rib];

    const int j0 = half * 128 + 4 * lane;       // first element this lane owns

    // ---- load 4 contiguous elements, exp, register exclusive prefix ----
    const float4 a = *(const float4*)(feaR + row * W_DIM + j0);
    const float p0 = __expf(a.x), p1 = __expf(a.y),
                p2 = __expf(a.z), p3 = __expf(a.w);
    const float jf = (float)j0;
    const float ep1 = p0,       eq1 = jf * p0;
    const float ep2 = ep1 + p1, eq2 = fmaf(jf + 1.0f, p1, eq1);
    const float ep3 = ep2 + p2, eq3 = fmaf(jf + 2.0f, p2, eq2);
    const float tp  = ep3 + p3, tq  = fmaf(jf + 3.0f, p3, eq3);

    // ---- warp inclusive scan of lane totals ----
    float ip = tp, iq = tq;
    #pragma unroll
    for (int off = 1; off < 32; off <<= 1) {
        const float sp = __shfl_up_sync(FULLM, ip, off);
        const float sq = __shfl_up_sync(FULLM, iq, off);
        if (lane >= off) { ip += sp; iq += sq; }
    }

    if (half == 0 && lane == 31) sTot[rib] = make_float2(ip, iq);
    __syncthreads();

    // Globally-correct base offset for this lane's entries.
    const float addp = half ? sTot[rib].x : 0.0f;
    const float addq = half ? sTot[rib].y : 0.0f;
    const float bp = (ip - tp) + addp;          // exclusive offset, global
    const float bq = (iq - tq) + addq;

    // ---- write E[j0..j0+4) = (P, Q) pairs; two STS.128 ----
    const float4 v0 = make_float4(bp,       bq,       ep1 + bp, eq1 + bq);
    const float4 v1 = make_float4(ep2 + bp, eq2 + bq, ep3 + bp, eq3 + bq);
    *(float4*)&E[j0]     = v0;
    *(float4*)&E[j0 + 2] = v1;
    if (half == 1 && lane == 31) E[W_DIM] = make_float2(ip + addp, iq + addq);

    // ---- left channel: constant fill (independent of scan) ----
    {
        const float4 cst = make_float4(mean_d, mean_d, mean_d, mean_d);
        *(float4*)(out + (cr * H_DIM + h) * W_DIM + j0) = cst;
    }
    __syncthreads();

    // ---- 4 outputs per lane at w = half*128 + 32*i + lane ----
    float* outR = out + ((cr + C_CH) * H_DIM + h) * W_DIM;
    const float wf0 = (float)(half * 128 + lane);
    #pragma unroll
    for (int i = 0; i < 4; ++i) {
        const int gw = half * 128 + 32 * i;     // warp-uniform group base
        const int w  = gw + lane;
        const float wf = wf0 + (float)(32 * i);
        if (gw >= dmax - 1) {
            // Full window: nv = D, invalid terms vanish, Sv = S_total.
            const int jlo = w - dmax + 1;
            const float2 lo = E[jlo];
            const float2 hi = E[jlo + D];
            const float denv = hi.x - lo.x;
            const float qd   = hi.y - lo.y;
            outR[w] = wf - __fdividef(qd, denv);
        } else {
            // General path (dlo = dmin always, since w - 255 <= 0 <= dmin).
            const int dhi = (dmax - 1) < w ? (dmax - 1) : w;
            int nv  = dhi - dmin + 1;
            if (nv < 0) nv = 0;
            int jhi1 = w - dmin + 1; if (jhi1 < 0) jhi1 = 0;
            int jlo  = w - dhi;      if (jlo > jhi1) jlo = jhi1;
            const float2 lo = E[jlo];
            const float2 hi = E[jhi1];
            const float denv = hi.x - lo.x;
            const float qd   = hi.y - lo.y;
            const float Sv  = 0.5f * (float)(dmin + dhi) * (float)nv;
            const float num = fmaf(wf, denv, S_total - Sv) - qd;
            const float den = denv + (float)(D - nv);
            outR[w] = __fdividef(num, den);
        }
    }
}

extern "C" void kernel_launch(void* const* d_in, const int* in_sizes, int n_in,
                              void* d_out, int out_size) {
    // metadata order: feaL (unused), feaR, min_disp, max_disp
    const float* feaR = (const float*)d_in[1];
    const int* p_min  = (const int*)d_in[2];
    const int* p_max  = (const int*)d_in[3];
    float* out = (float*)d_out;

    const int rows = C_CH * H_DIM;                       // 4096
    gcnet_v7_kernel<<<rows / ROWS_PER_BLOCK, 256>>>(feaR, p_min, p_max, out);
}